// round 1
// baseline (speedup 1.0000x reference)
#include <cuda_runtime.h>
#include <math.h>

#define Bq  16
#define Cc  256
#define NHh 8
#define KDd 32
#define Nn  4096
#define Hh  64
#define Ww  64
#define AGg 64

// ---------------- scratch (device globals; no allocation allowed) -----------
__device__ float g_qkv[(size_t)Bq * 768 * Nn];           // 201 MB: BN'd qkv, (B, 768, N)
__device__ float g_a[Bq * NHh * KDd * AGg];              // a[b][nh][kd][g]
__device__ float g_pb[NHh * AGg * Nn];                   // pb[nh][g][n]
__device__ float g_ab[NHh * AGg * Nn];                   // ab[nh][g][n]
__device__ float g_p[(size_t)Bq * NHh * AGg * Nn];       // 134 MB: logits -> probs
__device__ float g_attn[Bq * NHh * AGg * KDd];           // attn[b][nh][g][kd]
__device__ float g_out[(size_t)Bq * Cc * Nn];            // 67 MB: pre-proj output

// ---------------- GEMM + BN epilogue: Y[b][m][n] = BN(sum_k W[m][k] X[b][k][n])
__global__ __launch_bounds__(256) void gemm_bn(
    const float* __restrict__ X, const float* __restrict__ Wm,
    const float* __restrict__ bnp, float* __restrict__ Y,
    int M, int K, int NN)
{
    __shared__ float Ws[16][65];
    __shared__ float Xs[16][64];
    int mBase = blockIdx.y * 64, nBase = blockIdx.x * 64, b = blockIdx.z;
    const float* Xb = X + (size_t)b * K * NN;
    float* Yb = Y + (size_t)b * M * NN;
    int tx = threadIdx.x, ty = threadIdx.y;
    int tid = ty * 16 + tx;
    float acc[4][4] = {};
    for (int k0 = 0; k0 < K; k0 += 16) {
        #pragma unroll
        for (int i = tid; i < 64 * 16; i += 256) {
            int m = i >> 4, kk = i & 15;
            Ws[kk][m] = Wm[(size_t)(mBase + m) * K + k0 + kk];
        }
        #pragma unroll
        for (int i = tid; i < 16 * 64; i += 256) {
            int kk = i >> 6, n = i & 63;
            Xs[kk][n] = Xb[(size_t)(k0 + kk) * NN + nBase + n];
        }
        __syncthreads();
        #pragma unroll
        for (int kk = 0; kk < 16; kk++) {
            float wr[4], xr[4];
            #pragma unroll
            for (int i = 0; i < 4; i++) wr[i] = Ws[kk][ty * 4 + i];
            #pragma unroll
            for (int i = 0; i < 4; i++) xr[i] = Xs[kk][tx * 4 + i];
            #pragma unroll
            for (int i = 0; i < 4; i++)
                #pragma unroll
                for (int j = 0; j < 4; j++) acc[i][j] += wr[i] * xr[j];
        }
        __syncthreads();
    }
    #pragma unroll
    for (int i = 0; i < 4; i++) {
        int m = mBase + ty * 4 + i;
        float gg = bnp[m], bb = bnp[M + m], mm = bnp[2 * M + m], vv = bnp[3 * M + m];
        float inv  = gg * rsqrtf(vv + 1e-5f);
        float bias = bb - mm * inv;
        #pragma unroll
        for (int j = 0; j < 4; j++)
            Yb[(size_t)m * NN + nBase + tx * 4 + j] = acc[i][j] * inv + bias;
    }
}

// ---------------- pooling: a[b][nh][kd][g], replicating the reshape quirk ----
__global__ __launch_bounds__(256) void pool_kernel()
{
    int b = blockIdx.y, g = blockIdx.x, c = threadIdx.x;
    int gh = g >> 3, gw = g & 7;
    float s = 0.f;
    for (int hh = 0; hh < 8; hh++) {
        int h = gh * 8 + hh;
        for (int ww2 = 0; ww2 < 8; ww2++) {
            int w = gw * 8 + ww2;
            int flat = (h * Ww + w) * Cc + c;      // q-flat index
            int nh = flat >> 17;                   // / (KD*N)
            int kd = (flat >> 12) & 31;            // / N % KD
            int n  = flat & 4095;
            s += g_qkv[((size_t)(b * 768 + nh * 96 + kd)) * Nn + n];
        }
    }
    g_a[((b * NHh + (c >> 5)) * KDd + (c & 31)) * AGg + g] = s * (1.f / 64.f);
}

// ---------------- bilinear 7x7 -> 64x64 (jax half-pixel + edge clamp) --------
__device__ __forceinline__ float bilin7(const float* __restrict__ p, int oy, int ox)
{
    float uy = (oy + 0.5f) * (7.f / 64.f) - 0.5f;
    float ux = (ox + 0.5f) * (7.f / 64.f) - 0.5f;
    float fy = floorf(uy), fx = floorf(ux);
    int y0 = (int)fy, x0 = (int)fx;
    float ty = uy - fy, tx = ux - fx;
    int y0c = min(6, max(0, y0)),     y1c = min(6, max(0, y0 + 1));
    int x0c = min(6, max(0, x0)),     x1c = min(6, max(0, x0 + 1));
    float v00 = p[y0c * 7 + x0c], v01 = p[y0c * 7 + x1c];
    float v10 = p[y1c * 7 + x0c], v11 = p[y1c * 7 + x1c];
    return (v00 * (1.f - tx) + v01 * tx) * (1.f - ty)
         + (v10 * (1.f - tx) + v11 * tx) * ty;
}

__global__ __launch_bounds__(256) void pb_kernel(
    const float* __restrict__ an, const float* __restrict__ ah, const float* __restrict__ aw)
{
    int nh = blockIdx.z, g = blockIdx.y;
    int n = blockIdx.x * 256 + threadIdx.x;
    int h = n >> 6, w = n & 63;
    float v = bilin7(an + (nh * AGg + g) * 49, h, w)
            + ah[(nh * AGg + g) * Hh + h] + aw[(nh * AGg + g) * Ww + w];
    g_pb[(size_t)(nh * AGg + g) * Nn + n] = v;
}

__global__ __launch_bounds__(256) void ab_kernel(
    const float* __restrict__ na, const float* __restrict__ ha, const float* __restrict__ wa)
{
    int nh = blockIdx.z, g = blockIdx.y;
    int n = blockIdx.x * 256 + threadIdx.x;
    int h = n >> 6, w = n & 63;
    float v = bilin7(na + (nh * AGg + g) * 49, h, w)
            + ha[(nh * Hh + h) * AGg + g] + wa[(nh * Ww + w) * AGg + g];
    g_ab[(size_t)(nh * AGg + g) * Nn + n] = v;
}

// ---------------- attention-1 logits: p[b][nh][g][n] = scale*a.k + pb --------
__global__ __launch_bounds__(256) void logits_kernel()
{
    int b = blockIdx.z, nh = blockIdx.y;
    int n0 = blockIdx.x * 256;
    int t = threadIdx.x;
    __shared__ float a_s[32][64];
    __shared__ float k_s[32][256];
    for (int i = t; i < 32 * 64; i += 256)
        a_s[i >> 6][i & 63] = g_a[((b * NHh + nh) * KDd + (i >> 6)) * AGg + (i & 63)];
    const float* kbase = g_qkv + (size_t)(b * 768 + nh * 96 + 32) * Nn + n0;
    for (int i = t; i < 32 * 256; i += 256) {
        int kk = i >> 8, nn = i & 255;
        k_s[kk][nn] = kbase[(size_t)kk * Nn + nn];
    }
    __syncthreads();
    const float scale = 0.17677669529663687f;
    float* pout = g_p + (size_t)(b * NHh + nh) * AGg * Nn + n0 + t;
    const float* pbias = g_pb + (size_t)nh * AGg * Nn + n0 + t;
    #pragma unroll 4
    for (int g = 0; g < 64; g++) {
        float acc = 0.f;
        #pragma unroll
        for (int kd = 0; kd < 32; kd++) acc += a_s[kd][g] * k_s[kd][t];
        pout[(size_t)g * Nn] = acc * scale + pbias[(size_t)g * Nn];
    }
}

// ---------------- softmax over 4096-length rows (in place) -------------------
__global__ __launch_bounds__(256) void softmax_rows()
{
    int row = blockIdx.x;
    float* r = g_p + (size_t)row * Nn;
    int t = threadIdx.x;
    __shared__ float red[256];
    float mx = -1e30f;
    for (int i = t; i < Nn; i += 256) mx = fmaxf(mx, r[i]);
    red[t] = mx; __syncthreads();
    for (int s = 128; s > 0; s >>= 1) { if (t < s) red[t] = fmaxf(red[t], red[t + s]); __syncthreads(); }
    mx = red[0]; __syncthreads();
    float sum = 0.f;
    for (int i = t; i < Nn; i += 256) { float e = expf(r[i] - mx); r[i] = e; sum += e; }
    red[t] = sum; __syncthreads();
    for (int s = 128; s > 0; s >>= 1) { if (t < s) red[t] += red[t + s]; __syncthreads(); }
    float inv = 1.f / red[0];
    for (int i = t; i < Nn; i += 256) r[i] *= inv;
}

// ---------------- attn[b][nh][g][kd] = sum_n p[g][n] * v[kd][n] --------------
__global__ __launch_bounds__(256) void attn_pv_kernel()
{
    int bh = blockIdx.x; int b = bh >> 3, nh = bh & 7;
    __shared__ float v_s[64][33];
    __shared__ float p_s[64][64];
    int t = threadIdx.x;
    int kd = t & 31, gb = t >> 5;
    float acc[8];
    #pragma unroll
    for (int j = 0; j < 8; j++) acc[j] = 0.f;
    const float* pbase = g_p   + (size_t)(b * NHh + nh) * AGg * Nn;
    const float* vbase = g_qkv + (size_t)(b * 768 + nh * 96 + 64) * Nn;
    for (int n0 = 0; n0 < Nn; n0 += 64) {
        for (int i = t; i < 32 * 64; i += 256) {
            int vkd = i >> 6, vn = i & 63;
            v_s[vn][vkd] = vbase[(size_t)vkd * Nn + n0 + vn];
        }
        for (int i = t; i < 64 * 64; i += 256) {
            int pg = i >> 6, pn = i & 63;
            p_s[pg][pn] = pbase[(size_t)pg * Nn + n0 + pn];
        }
        __syncthreads();
        #pragma unroll 8
        for (int nn = 0; nn < 64; nn++) {
            float vv = v_s[nn][kd];
            #pragma unroll
            for (int j = 0; j < 8; j++) acc[j] += p_s[gb * 8 + j][nn] * vv;
        }
        __syncthreads();
    }
    #pragma unroll
    for (int j = 0; j < 8; j++)
        g_attn[((b * NHh + nh) * AGg + gb * 8 + j) * KDd + kd] = acc[j];
}

// ---------------- fused attention-2: softmax over AG + output contraction ----
__global__ __launch_bounds__(256) void attn2_out_kernel()
{
    int b = blockIdx.z, nh = blockIdx.y;
    int n = blockIdx.x * 256 + threadIdx.x;
    int t = threadIdx.x;
    __shared__ float a_s[32][64];    // a[kd][g]
    __shared__ float at_s[64][32];   // attn[g][kd]
    for (int i = t; i < 2048; i += 256) {
        a_s[i >> 6][i & 63]  = g_a[((b * NHh + nh) * KDd) * AGg + i];
        at_s[i >> 5][i & 31] = g_attn[((b * NHh + nh) * AGg) * KDd + i];
    }
    __syncthreads();
    float qreg[32];
    #pragma unroll
    for (int kd = 0; kd < 32; kd++)
        qreg[kd] = g_qkv[((size_t)(b * 768 + nh * 96 + kd)) * Nn + n];
    const float scale = 0.17677669529663687f;
    float lg[64];
    #pragma unroll
    for (int g = 0; g < 64; g++) {
        float acc = 0.f;
        #pragma unroll
        for (int kd = 0; kd < 32; kd++) acc += qreg[kd] * a_s[kd][g];
        lg[g] = acc * scale + g_ab[(size_t)(nh * AGg + g) * Nn + n];
    }
    float mx = -1e30f;
    #pragma unroll
    for (int g = 0; g < 64; g++) mx = fmaxf(mx, lg[g]);
    float sum = 0.f;
    #pragma unroll
    for (int g = 0; g < 64; g++) { lg[g] = expf(lg[g] - mx); sum += lg[g]; }
    float inv = 1.f / sum;
    #pragma unroll
    for (int kd = 0; kd < 32; kd++) {
        float acc = 0.f;
        #pragma unroll
        for (int g = 0; g < 64; g++) acc += lg[g] * at_s[g][kd];
        g_out[((size_t)(b * Cc + nh * KDd + kd)) * Nn + n] = acc * inv;
    }
}

// ---------------- depthwise 3x3 pe conv + BN, added into g_out ---------------
__global__ __launch_bounds__(256) void pe_kernel(
    const float* __restrict__ pw, const float* __restrict__ bnp)
{
    int b = blockIdx.z, c = blockIdx.y;
    int n = blockIdx.x * 256 + threadIdx.x;
    int h = n >> 6, w = n & 63;
    const float* vb = g_qkv + (size_t)(b * 768 + (c >> 5) * 96 + 64 + (c & 31)) * Nn;
    float acc = 0.f;
    #pragma unroll
    for (int dy = -1; dy <= 1; dy++) {
        int hy = h + dy; if (hy < 0 || hy >= 64) continue;
        #pragma unroll
        for (int dx = -1; dx <= 1; dx++) {
            int wx = w + dx; if (wx < 0 || wx >= 64) continue;
            acc += vb[hy * 64 + wx] * pw[c * 9 + (dy + 1) * 3 + (dx + 1)];
        }
    }
    float gg = bnp[c], bb = bnp[Cc + c], mm = bnp[2 * Cc + c], vv = bnp[3 * Cc + c];
    float inv = gg * rsqrtf(vv + 1e-5f);
    g_out[(size_t)(b * Cc + c) * Nn + n] += acc * inv + (bb - mm * inv);
}

// -----------------------------------------------------------------------------
extern "C" void kernel_launch(void* const* d_in, const int* in_sizes, int n_in,
                              void* d_out, int out_size)
{
    const float* x       = (const float*)d_in[0];
    const float* qkv_w   = (const float*)d_in[1];
    const float* qkv_bn  = (const float*)d_in[2];
    const float* pe_w    = (const float*)d_in[3];
    const float* pe_bn   = (const float*)d_in[4];
    const float* proj_w  = (const float*)d_in[5];
    const float* proj_bn = (const float*)d_in[6];
    const float* an_bias = (const float*)d_in[7];
    const float* na_bias = (const float*)d_in[8];
    const float* ah_bias = (const float*)d_in[9];
    const float* aw_bias = (const float*)d_in[10];
    const float* ha_bias = (const float*)d_in[11];
    const float* wa_bias = (const float*)d_in[12];
    float* out = (float*)d_out;

    float *qkv_ptr, *out_ptr;
    cudaGetSymbolAddress((void**)&qkv_ptr, g_qkv);
    cudaGetSymbolAddress((void**)&out_ptr, g_out);

    dim3 blk2(16, 16);
    // 1. qkv GEMM + BN : (768x256) x (256x4096) per batch
    gemm_bn<<<dim3(64, 12, 16), blk2>>>(x, qkv_w, qkv_bn, qkv_ptr, 768, 256, 4096);
    // 2. pooling -> a
    pool_kernel<<<dim3(64, 16), 256>>>();
    // 3. bias maps
    pb_kernel<<<dim3(16, 64, 8), 256>>>(an_bias, ah_bias, aw_bias);
    ab_kernel<<<dim3(16, 64, 8), 256>>>(na_bias, ha_bias, wa_bias);
    // 4. attention-1 logits
    logits_kernel<<<dim3(16, 8, 16), 256>>>();
    // 5. softmax over N
    softmax_rows<<<16 * 8 * 64, 256>>>();
    // 6. attn = P V^T
    attn_pv_kernel<<<128, 256>>>();
    // 7. fused attention-2 + output
    attn2_out_kernel<<<dim3(16, 8, 16), 256>>>();
    // 8. depthwise pe conv + BN add
    pe_kernel<<<dim3(16, 256, 16), 256>>>(pe_w, pe_bn);
    // 9. proj GEMM + BN -> final output
    gemm_bn<<<dim3(64, 4, 16), blk2>>>(out_ptr, proj_w, proj_bn, out, 256, 256, 4096);
}

// round 2
// speedup vs baseline: 1.3492x; 1.3492x over previous
#include <cuda_runtime.h>
#include <math.h>

#define Bq  16
#define Cc  256
#define NHh 8
#define KDd 32
#define Nn  4096
#define Hh  64
#define Ww  64
#define AGg 64

// ---------------- scratch (device globals; no allocation allowed) -----------
__device__ float g_qkv[(size_t)Bq * 768 * Nn];           // BN'd qkv, (B, 768, N)
__device__ float g_a[Bq * NHh * KDd * AGg];              // a[b][nh][kd][g]
__device__ float g_pb[NHh * AGg * Nn];                   // pb[nh][g][n]
__device__ float g_ab[NHh * AGg * Nn];                   // ab[nh][g][n]
__device__ float g_attn[Bq * NHh * AGg * KDd];           // attn[b][nh][g][kd]
__device__ float g_out[(size_t)Bq * Cc * Nn];            // pre-proj output

// ---------------- 128x128 GEMM + BN: Y[b][m][n] = BN(sum_k W[m][k] X[b][k][n])
__global__ __launch_bounds__(256) void gemm_bn_128(
    const float* __restrict__ X, const float* __restrict__ Wm,
    const float* __restrict__ bnp, float* __restrict__ Y,
    int M, int K, int NN)
{
    __shared__ float As[2][8][128];
    __shared__ float Bs[2][8][128];
    int b = blockIdx.z;
    int mBase = blockIdx.y * 128, nBase = blockIdx.x * 128;
    const float* Xb = X + (size_t)b * K * NN;
    float* Yb = Y + (size_t)b * M * NN;
    int tid = threadIdx.x;
    int tx = tid & 15, ty = tid >> 4;
    int am = tid >> 1, ak = (tid & 1) * 4;        // A load: 128 m x 8 k
    int bk = tid >> 5, bn = (tid & 31) * 4;       // B load: 8 k x 128 n

    float acc[8][8];
    #pragma unroll
    for (int i = 0; i < 8; i++)
        #pragma unroll
        for (int j = 0; j < 8; j++) acc[i][j] = 0.f;

    // prologue: load k0 = 0 into buffer 0
    {
        float4 av = *(const float4*)&Wm[(size_t)(mBase + am) * K + ak];
        As[0][ak + 0][am] = av.x; As[0][ak + 1][am] = av.y;
        As[0][ak + 2][am] = av.z; As[0][ak + 3][am] = av.w;
        *(float4*)&Bs[0][bk][bn] =
            *(const float4*)&Xb[(size_t)bk * NN + nBase + bn];
    }
    __syncthreads();

    int buf = 0;
    for (int k0 = 8; k0 <= K; k0 += 8) {
        int nbuf = buf ^ 1;
        if (k0 < K) {
            float4 av = *(const float4*)&Wm[(size_t)(mBase + am) * K + k0 + ak];
            As[nbuf][ak + 0][am] = av.x; As[nbuf][ak + 1][am] = av.y;
            As[nbuf][ak + 2][am] = av.z; As[nbuf][ak + 3][am] = av.w;
            *(float4*)&Bs[nbuf][bk][bn] =
                *(const float4*)&Xb[(size_t)(k0 + bk) * NN + nBase + bn];
        }
        #pragma unroll
        for (int kk = 0; kk < 8; kk++) {
            float ar[8], br[8];
            *(float4*)&ar[0] = *(float4*)&As[buf][kk][ty * 8];
            *(float4*)&ar[4] = *(float4*)&As[buf][kk][ty * 8 + 4];
            *(float4*)&br[0] = *(float4*)&Bs[buf][kk][tx * 8];
            *(float4*)&br[4] = *(float4*)&Bs[buf][kk][tx * 8 + 4];
            #pragma unroll
            for (int i = 0; i < 8; i++)
                #pragma unroll
                for (int j = 0; j < 8; j++) acc[i][j] += ar[i] * br[j];
        }
        __syncthreads();
        buf = nbuf;
    }

    #pragma unroll
    for (int i = 0; i < 8; i++) {
        int m = mBase + ty * 8 + i;
        float gg = bnp[m], bb = bnp[M + m], mm = bnp[2 * M + m], vv = bnp[3 * M + m];
        float inv  = gg * rsqrtf(vv + 1e-5f);
        float bias = bb - mm * inv;
        float* yrow = Yb + (size_t)m * NN + nBase + tx * 8;
        float4 o0, o1;
        o0.x = acc[i][0] * inv + bias; o0.y = acc[i][1] * inv + bias;
        o0.z = acc[i][2] * inv + bias; o0.w = acc[i][3] * inv + bias;
        o1.x = acc[i][4] * inv + bias; o1.y = acc[i][5] * inv + bias;
        o1.z = acc[i][6] * inv + bias; o1.w = acc[i][7] * inv + bias;
        *(float4*)yrow = o0;
        *(float4*)(yrow + 4) = o1;
    }
}

// ---------------- pooling: a[b][nh][kd][g], replicating the reshape quirk ----
__global__ __launch_bounds__(256) void pool_kernel()
{
    int b = blockIdx.y, g = blockIdx.x, c = threadIdx.x;
    int gh = g >> 3, gw = g & 7;
    float s = 0.f;
    for (int hh = 0; hh < 8; hh++) {
        int h = gh * 8 + hh;
        for (int ww2 = 0; ww2 < 8; ww2++) {
            int w = gw * 8 + ww2;
            int flat = (h * Ww + w) * Cc + c;      // q-flat index
            int nh = flat >> 17;
            int kd = (flat >> 12) & 31;
            int n  = flat & 4095;
            s += g_qkv[((size_t)(b * 768 + nh * 96 + kd)) * Nn + n];
        }
    }
    g_a[((b * NHh + (c >> 5)) * KDd + (c & 31)) * AGg + g] = s * (1.f / 64.f);
}

// ---------------- bilinear 7x7 -> 64x64 (jax half-pixel + edge clamp) --------
__device__ __forceinline__ float bilin7(const float* __restrict__ p, int oy, int ox)
{
    float uy = (oy + 0.5f) * (7.f / 64.f) - 0.5f;
    float ux = (ox + 0.5f) * (7.f / 64.f) - 0.5f;
    float fy = floorf(uy), fx = floorf(ux);
    int y0 = (int)fy, x0 = (int)fx;
    float ty = uy - fy, tx = ux - fx;
    int y0c = min(6, max(0, y0)),     y1c = min(6, max(0, y0 + 1));
    int x0c = min(6, max(0, x0)),     x1c = min(6, max(0, x0 + 1));
    float v00 = p[y0c * 7 + x0c], v01 = p[y0c * 7 + x1c];
    float v10 = p[y1c * 7 + x0c], v11 = p[y1c * 7 + x1c];
    return (v00 * (1.f - tx) + v01 * tx) * (1.f - ty)
         + (v10 * (1.f - tx) + v11 * tx) * ty;
}

__global__ __launch_bounds__(256) void pb_kernel(
    const float* __restrict__ an, const float* __restrict__ ah, const float* __restrict__ aw)
{
    int nh = blockIdx.z, g = blockIdx.y;
    int n = blockIdx.x * 256 + threadIdx.x;
    int h = n >> 6, w = n & 63;
    float v = bilin7(an + (nh * AGg + g) * 49, h, w)
            + ah[(nh * AGg + g) * Hh + h] + aw[(nh * AGg + g) * Ww + w];
    g_pb[(size_t)(nh * AGg + g) * Nn + n] = v;
}

__global__ __launch_bounds__(256) void ab_kernel(
    const float* __restrict__ na, const float* __restrict__ ha, const float* __restrict__ wa)
{
    int nh = blockIdx.z, g = blockIdx.y;
    int n = blockIdx.x * 256 + threadIdx.x;
    int h = n >> 6, w = n & 63;
    float v = bilin7(na + (nh * AGg + g) * 49, h, w)
            + ha[(nh * Hh + h) * AGg + g] + wa[(nh * Ww + w) * AGg + g];
    g_ab[(size_t)(nh * AGg + g) * Nn + n] = v;
}

// ---------------- fused attention-1: logits + online softmax + P*V^T ---------
// one block per (b, nh); 256 threads; N chunked by 64
__global__ __launch_bounds__(256) void attn1_fused()
{
    int bh = blockIdx.x; int b = bh >> 3, nh = bh & 7;
    __shared__ float a_s[32][64];     // a[kd][g]
    __shared__ float S[64][68];       // logits -> probs (row stride 68: 16B-aligned)
    __shared__ float k_s[32][65];
    __shared__ float v_s[64][33];
    __shared__ float m_sh[64], l_sh[64], fact[64];
    int t = threadIdx.x;
    int lane = t & 31, wid = t >> 5;

    for (int i = t; i < 2048; i += 256)
        a_s[i >> 6][i & 63] = g_a[((b * NHh + nh) * KDd) * AGg + i];
    if (t < 64) { m_sh[t] = -1e30f; l_sh[t] = 0.f; }

    const float* kbase = g_qkv + (size_t)(b * 768 + nh * 96 + 32) * Nn;
    const float* vbase = g_qkv + (size_t)(b * 768 + nh * 96 + 64) * Nn;
    const float* pbase = g_pb + (size_t)nh * AGg * Nn;
    const float scale = 0.17677669529663687f;

    float acc[8];
    #pragma unroll
    for (int j = 0; j < 8; j++) acc[j] = 0.f;

    int ln = t & 63, gs = t >> 6;     // logits mapping: column ln, 16 g rows

    for (int n0 = 0; n0 < Nn; n0 += 64) {
        for (int i = t; i < 2048; i += 256) {
            int ck = i >> 6, cn = i & 63;
            float kv = kbase[(size_t)ck * Nn + n0 + cn];
            float vv = vbase[(size_t)ck * Nn + n0 + cn];
            k_s[ck][cn] = kv;
            v_s[cn][ck] = vv;
        }
        __syncthreads();

        // ---- logits: S[g][ln] for g in [gs*16, gs*16+16)
        {
            float kcol[32];
            #pragma unroll
            for (int c = 0; c < 32; c++) kcol[c] = k_s[c][ln];
            float accl[16];
            #pragma unroll
            for (int gi = 0; gi < 16; gi++) accl[gi] = 0.f;
            #pragma unroll
            for (int c = 0; c < 32; c++) {
                float kc = kcol[c];
                const float4* arow = (const float4*)&a_s[c][gs * 16];
                float4 a0 = arow[0], a1 = arow[1], a2 = arow[2], a3 = arow[3];
                accl[0]  += kc * a0.x; accl[1]  += kc * a0.y;
                accl[2]  += kc * a0.z; accl[3]  += kc * a0.w;
                accl[4]  += kc * a1.x; accl[5]  += kc * a1.y;
                accl[6]  += kc * a1.z; accl[7]  += kc * a1.w;
                accl[8]  += kc * a2.x; accl[9]  += kc * a2.y;
                accl[10] += kc * a2.z; accl[11] += kc * a2.w;
                accl[12] += kc * a3.x; accl[13] += kc * a3.y;
                accl[14] += kc * a3.z; accl[15] += kc * a3.w;
            }
            #pragma unroll
            for (int gi = 0; gi < 16; gi++) {
                int g = gs * 16 + gi;
                S[g][ln] = accl[gi] * scale + pbase[(size_t)g * Nn + n0 + ln];
            }
        }
        __syncthreads();

        // ---- online softmax stats per row; warp w owns rows w*8..w*8+7
        #pragma unroll
        for (int j = 0; j < 8; j++) {
            int g = wid * 8 + j;
            float v0 = S[g][lane], v1 = S[g][lane + 32];
            float mx = fmaxf(v0, v1);
            #pragma unroll
            for (int o = 16; o > 0; o >>= 1) mx = fmaxf(mx, __shfl_xor_sync(~0u, mx, o));
            float mold = m_sh[g];
            float mnew = fmaxf(mold, mx);
            float e0 = __expf(v0 - mnew), e1 = __expf(v1 - mnew);
            S[g][lane] = e0; S[g][lane + 32] = e1;
            float s = e0 + e1;
            #pragma unroll
            for (int o = 16; o > 0; o >>= 1) s += __shfl_xor_sync(~0u, s, o);
            if (lane == 0) {
                float f = __expf(mold - mnew);
                l_sh[g] = l_sh[g] * f + s;
                m_sh[g] = mnew;
                fact[g] = f;
            }
        }
        __syncthreads();

        // ---- accumulate: kd = lane, rows wid*8+j
        {
            float a2[8];
            #pragma unroll
            for (int j = 0; j < 8; j++) a2[j] = acc[j] * fact[wid * 8 + j];
            #pragma unroll 4
            for (int nb = 0; nb < 64; nb += 4) {
                float vv0 = v_s[nb + 0][lane], vv1 = v_s[nb + 1][lane];
                float vv2 = v_s[nb + 2][lane], vv3 = v_s[nb + 3][lane];
                #pragma unroll
                for (int j = 0; j < 8; j++) {
                    float4 s4 = *(const float4*)&S[wid * 8 + j][nb];
                    a2[j] += s4.x * vv0 + s4.y * vv1 + s4.z * vv2 + s4.w * vv3;
                }
            }
            #pragma unroll
            for (int j = 0; j < 8; j++) acc[j] = a2[j];
        }
        __syncthreads();
    }

    #pragma unroll
    for (int j = 0; j < 8; j++) {
        int g = wid * 8 + j;
        g_attn[((b * NHh + nh) * AGg + g) * KDd + lane] = acc[j] / l_sh[g];
    }
}

// ---------------- fused attention-2: softmax over AG + output contraction ----
__global__ __launch_bounds__(256) void attn2_out_kernel()
{
    int b = blockIdx.z, nh = blockIdx.y;
    int n = blockIdx.x * 256 + threadIdx.x;
    int t = threadIdx.x;
    __shared__ float a_s[32][64];    // a[kd][g]
    __shared__ float at_s[64][32];   // attn[g][kd]
    for (int i = t; i < 2048; i += 256) {
        a_s[i >> 6][i & 63]  = g_a[((b * NHh + nh) * KDd) * AGg + i];
        at_s[i >> 5][i & 31] = g_attn[((b * NHh + nh) * AGg) * KDd + i];
    }
    __syncthreads();
    float qreg[32];
    #pragma unroll
    for (int kd = 0; kd < 32; kd++)
        qreg[kd] = g_qkv[((size_t)(b * 768 + nh * 96 + kd)) * Nn + n];
    const float scale = 0.17677669529663687f;
    float lg[64];
    #pragma unroll
    for (int g = 0; g < 64; g++) {
        float acc = 0.f;
        #pragma unroll
        for (int kd = 0; kd < 32; kd++) acc += qreg[kd] * a_s[kd][g];
        lg[g] = acc * scale + g_ab[(size_t)(nh * AGg + g) * Nn + n];
    }
    float mx = -1e30f;
    #pragma unroll
    for (int g = 0; g < 64; g++) mx = fmaxf(mx, lg[g]);
    float sum = 0.f;
    #pragma unroll
    for (int g = 0; g < 64; g++) { lg[g] = __expf(lg[g] - mx); sum += lg[g]; }
    float inv = 1.f / sum;
    #pragma unroll
    for (int kd = 0; kd < 32; kd++) {
        float acc = 0.f;
        #pragma unroll
        for (int g = 0; g < 64; g++) acc += lg[g] * at_s[g][kd];
        g_out[((size_t)(b * Cc + nh * KDd + kd)) * Nn + n] = acc * inv;
    }
}

// ---------------- depthwise 3x3 pe conv + BN, added into g_out ---------------
__global__ __launch_bounds__(256) void pe_kernel(
    const float* __restrict__ pw, const float* __restrict__ bnp)
{
    int b = blockIdx.z, c = blockIdx.y;
    int n = blockIdx.x * 256 + threadIdx.x;
    int h = n >> 6, w = n & 63;
    const float* vb = g_qkv + (size_t)(b * 768 + (c >> 5) * 96 + 64 + (c & 31)) * Nn;
    float acc = 0.f;
    #pragma unroll
    for (int dy = -1; dy <= 1; dy++) {
        int hy = h + dy; if (hy < 0 || hy >= 64) continue;
        #pragma unroll
        for (int dx = -1; dx <= 1; dx++) {
            int wx = w + dx; if (wx < 0 || wx >= 64) continue;
            acc += vb[hy * 64 + wx] * pw[c * 9 + (dy + 1) * 3 + (dx + 1)];
        }
    }
    float gg = bnp[c], bb = bnp[Cc + c], mm = bnp[2 * Cc + c], vv = bnp[3 * Cc + c];
    float inv = gg * rsqrtf(vv + 1e-5f);
    g_out[(size_t)(b * Cc + c) * Nn + n] += acc * inv + (bb - mm * inv);
}

// -----------------------------------------------------------------------------
extern "C" void kernel_launch(void* const* d_in, const int* in_sizes, int n_in,
                              void* d_out, int out_size)
{
    const float* x       = (const float*)d_in[0];
    const float* qkv_w   = (const float*)d_in[1];
    const float* qkv_bn  = (const float*)d_in[2];
    const float* pe_w    = (const float*)d_in[3];
    const float* pe_bn   = (const float*)d_in[4];
    const float* proj_w  = (const float*)d_in[5];
    const float* proj_bn = (const float*)d_in[6];
    const float* an_bias = (const float*)d_in[7];
    const float* na_bias = (const float*)d_in[8];
    const float* ah_bias = (const float*)d_in[9];
    const float* aw_bias = (const float*)d_in[10];
    const float* ha_bias = (const float*)d_in[11];
    const float* wa_bias = (const float*)d_in[12];
    float* out = (float*)d_out;

    float *qkv_ptr, *out_ptr;
    cudaGetSymbolAddress((void**)&qkv_ptr, g_qkv);
    cudaGetSymbolAddress((void**)&out_ptr, g_out);

    // 1. qkv GEMM + BN : (768x256) x (256x4096) per batch
    gemm_bn_128<<<dim3(32, 6, 16), 256>>>(x, qkv_w, qkv_bn, qkv_ptr, 768, 256, 4096);
    // 2. pooling -> a
    pool_kernel<<<dim3(64, 16), 256>>>();
    // 3. bias maps
    pb_kernel<<<dim3(16, 64, 8), 256>>>(an_bias, ah_bias, aw_bias);
    ab_kernel<<<dim3(16, 64, 8), 256>>>(na_bias, ha_bias, wa_bias);
    // 4. fused attention-1 (logits + online softmax + PV)
    attn1_fused<<<128, 256>>>();
    // 5. fused attention-2 + output
    attn2_out_kernel<<<dim3(16, 8, 16), 256>>>();
    // 6. depthwise pe conv + BN add
    pe_kernel<<<dim3(16, 256, 16), 256>>>(pe_w, pe_bn);
    // 7. proj GEMM + BN -> final output
    gemm_bn_128<<<dim3(32, 2, 16), 256>>>(out_ptr, proj_w, proj_bn, out, 256, 256, 4096);
}

// round 4
// speedup vs baseline: 1.7866x; 1.3241x over previous
#include <cuda_runtime.h>
#include <math.h>
#include <stdint.h>

#define Bq  16
#define Cc  256
#define NHh 8
#define KDd 32
#define Nn  4096
#define Hh  64
#define Ww  64
#define AGg 64

// ---------------- scratch (device globals; no allocation allowed) -----------
__device__ float g_qkv[(size_t)Bq * 768 * Nn];           // BN'd qkv, (B, 768, N)
__device__ float g_a[Bq * NHh * KDd * AGg];              // a[b][nh][kd][g]
__device__ float g_pb[NHh * AGg * Nn];                   // pb[nh][g][n]
__device__ float g_ab[NHh * AGg * Nn];                   // ab[nh][g][n]
__device__ float g_attn[Bq * NHh * AGg * KDd];           // attn[b][nh][g][kd]
__device__ float g_out[(size_t)Bq * Cc * Nn];            // pre-proj output

// ======================= tf32 mma.sync GEMM + BN ============================
// Y[b][m][n] = BN(sum_k W[m][k] * X[b][k][n])
// CTA: 128x128 tile, 256 threads (8 warps, 2x4), warp tile 64x32.
// K chunked by 32, double-buffered smem with register prefetch.
#define AS_STRIDE 36
#define BS_STRIDE 136
#define ABUF (128 * AS_STRIDE)
#define BBUF (32 * BS_STRIDE)
#define GEMM_SMEM ((ABUF + BBUF) * 2 * 4)

__device__ __forceinline__ uint32_t f2tf32(float f) {
    uint32_t r;
    asm("cvt.rna.tf32.f32 %0, %1;" : "=r"(r) : "f"(f));
    return r;
}

__device__ __forceinline__ void mma_tf32(float* c, const uint32_t* a, const uint32_t* b) {
    asm volatile(
        "mma.sync.aligned.m16n8k8.row.col.f32.tf32.tf32.f32 "
        "{%0,%1,%2,%3}, {%4,%5,%6,%7}, {%8,%9}, {%0,%1,%2,%3};"
        : "+f"(c[0]), "+f"(c[1]), "+f"(c[2]), "+f"(c[3])
        : "r"(a[0]), "r"(a[1]), "r"(a[2]), "r"(a[3]), "r"(b[0]), "r"(b[1]));
}

__global__ __launch_bounds__(256) void gemm_mma(
    const float* __restrict__ X, const float* __restrict__ Wm,
    const float* __restrict__ bnp, float* __restrict__ Y,
    int M, int K, int NN)
{
    extern __shared__ float sm[];
    float* As = sm;                 // [2][128][AS_STRIDE]
    float* Bs = sm + 2 * ABUF;      // [2][32][BS_STRIDE]
    int b = blockIdx.z, mBase = blockIdx.y * 128, nBase = blockIdx.x * 128;
    const float* Xb = X + (size_t)b * K * NN;
    float* Yb = Y + (size_t)b * M * NN;
    int tid = threadIdx.x, lane = tid & 31, wid = tid >> 5;
    int woffM = (wid >> 2) * 64, woffN = (wid & 3) * 32;

    // gmem load mapping
    int am = tid >> 1, ak = (tid & 1) * 16;     // A: 128 rows x 32 k
    int bk = tid >> 3, bn = (tid & 7) * 16;     // B: 32 k x 128 n

    float c[4][4][4];
    #pragma unroll
    for (int mt = 0; mt < 4; mt++)
        #pragma unroll
        for (int nt = 0; nt < 4; nt++)
            #pragma unroll
            for (int r = 0; r < 4; r++) c[mt][nt][r] = 0.f;

    // ---- prologue: chunk 0 -> buffer 0
    {
        const float4* wrow = (const float4*)(Wm + (size_t)(mBase + am) * K + ak);
        const float4* xrow = (const float4*)(Xb + (size_t)bk * NN + nBase + bn);
        #pragma unroll
        for (int f = 0; f < 4; f++) {
            float4 v = wrow[f];
            float* d = As + am * AS_STRIDE + ak + f * 4;
            d[0] = __uint_as_float(f2tf32(v.x)); d[1] = __uint_as_float(f2tf32(v.y));
            d[2] = __uint_as_float(f2tf32(v.z)); d[3] = __uint_as_float(f2tf32(v.w));
        }
        #pragma unroll
        for (int f = 0; f < 4; f++) {
            float4 v = xrow[f];
            float* d = Bs + bk * BS_STRIDE + bn + f * 4;
            d[0] = __uint_as_float(f2tf32(v.x)); d[1] = __uint_as_float(f2tf32(v.y));
            d[2] = __uint_as_float(f2tf32(v.z)); d[3] = __uint_as_float(f2tf32(v.w));
        }
    }
    __syncthreads();

    int nch = K >> 5;
    for (int ch = 0; ch < nch; ch++) {
        int buf = ch & 1;
        float* a  = As + buf * ABUF;
        float* bs = Bs + buf * BBUF;

        // prefetch next chunk into registers
        float4 wreg[4], xreg[4];
        if (ch + 1 < nch) {
            int k0 = (ch + 1) * 32;
            const float4* wrow = (const float4*)(Wm + (size_t)(mBase + am) * K + k0 + ak);
            const float4* xrow = (const float4*)(Xb + (size_t)(k0 + bk) * NN + nBase + bn);
            #pragma unroll
            for (int f = 0; f < 4; f++) { wreg[f] = wrow[f]; xreg[f] = xrow[f]; }
        }

        // compute on current buffer: 4 k8 steps
        #pragma unroll
        for (int ks = 0; ks < 4; ks++) {
            uint32_t af[4][4], bf[4][2];
            int ar = woffM + (lane >> 2);
            int ac = ks * 8 + (lane & 3);
            #pragma unroll
            for (int mt = 0; mt < 4; mt++) {
                const float* ab = a + (ar + mt * 16) * AS_STRIDE + ac;
                af[mt][0] = __float_as_uint(ab[0]);
                af[mt][1] = __float_as_uint(ab[8 * AS_STRIDE]);
                af[mt][2] = __float_as_uint(ab[4]);
                af[mt][3] = __float_as_uint(ab[8 * AS_STRIDE + 4]);
            }
            int br = ks * 8 + (lane & 3);
            int bc = woffN + (lane >> 2);
            #pragma unroll
            for (int nt = 0; nt < 4; nt++) {
                const float* bb = bs + br * BS_STRIDE + bc + nt * 8;
                bf[nt][0] = __float_as_uint(bb[0]);
                bf[nt][1] = __float_as_uint(bb[4 * BS_STRIDE]);
            }
            #pragma unroll
            for (int mt = 0; mt < 4; mt++)
                #pragma unroll
                for (int nt = 0; nt < 4; nt++)
                    mma_tf32(c[mt][nt], af[mt], bf[nt]);
        }

        // store prefetched chunk into the other buffer
        if (ch + 1 < nch) {
            int nb = buf ^ 1;
            float* an = As + nb * ABUF;
            float* bsn = Bs + nb * BBUF;
            #pragma unroll
            for (int f = 0; f < 4; f++) {
                float4 v = wreg[f];
                float* d = an + am * AS_STRIDE + ak + f * 4;
                d[0] = __uint_as_float(f2tf32(v.x)); d[1] = __uint_as_float(f2tf32(v.y));
                d[2] = __uint_as_float(f2tf32(v.z)); d[3] = __uint_as_float(f2tf32(v.w));
            }
            #pragma unroll
            for (int f = 0; f < 4; f++) {
                float4 v = xreg[f];
                float* d = bsn + bk * BS_STRIDE + bn + f * 4;
                d[0] = __uint_as_float(f2tf32(v.x)); d[1] = __uint_as_float(f2tf32(v.y));
                d[2] = __uint_as_float(f2tf32(v.z)); d[3] = __uint_as_float(f2tf32(v.w));
            }
        }
        __syncthreads();
    }

    // ---- epilogue: BN + store (C frag: c0/c1 = row r, cols 2q,2q+1; c2/c3 = row r+8)
    #pragma unroll
    for (int mt = 0; mt < 4; mt++) {
        int r0 = mBase + woffM + mt * 16 + (lane >> 2);
        int r1 = r0 + 8;
        float g0 = bnp[r0], b0 = bnp[M + r0], m0 = bnp[2 * M + r0], v0 = bnp[3 * M + r0];
        float g1 = bnp[r1], b1 = bnp[M + r1], m1 = bnp[2 * M + r1], v1 = bnp[3 * M + r1];
        float inv0 = g0 * rsqrtf(v0 + 1e-5f), bias0 = b0 - m0 * inv0;
        float inv1 = g1 * rsqrtf(v1 + 1e-5f), bias1 = b1 - m1 * inv1;
        #pragma unroll
        for (int nt = 0; nt < 4; nt++) {
            int n = nBase + woffN + nt * 8 + 2 * (lane & 3);
            float2 o0, o1;
            o0.x = c[mt][nt][0] * inv0 + bias0;
            o0.y = c[mt][nt][1] * inv0 + bias0;
            o1.x = c[mt][nt][2] * inv1 + bias1;
            o1.y = c[mt][nt][3] * inv1 + bias1;
            *(float2*)(Yb + (size_t)r0 * NN + n) = o0;
            *(float2*)(Yb + (size_t)r1 * NN + n) = o1;
        }
    }
}

// ---------------- pooling: a[b][nh][kd][g], replicating the reshape quirk ----
__global__ __launch_bounds__(256) void pool_kernel()
{
    int b = blockIdx.y, g = blockIdx.x, c = threadIdx.x;
    int gh = g >> 3, gw = g & 7;
    float s = 0.f;
    for (int hh = 0; hh < 8; hh++) {
        int h = gh * 8 + hh;
        for (int ww2 = 0; ww2 < 8; ww2++) {
            int w = gw * 8 + ww2;
            int flat = (h * Ww + w) * Cc + c;      // q-flat index
            int nh = flat >> 17;
            int kd = (flat >> 12) & 31;
            int n  = flat & 4095;
            s += g_qkv[((size_t)(b * 768 + nh * 96 + kd)) * Nn + n];
        }
    }
    g_a[((b * NHh + (c >> 5)) * KDd + (c & 31)) * AGg + g] = s * (1.f / 64.f);
}

// ---------------- bilinear 7x7 -> 64x64 (jax half-pixel + edge clamp) --------
__device__ __forceinline__ float bilin7(const float* __restrict__ p, int oy, int ox)
{
    float uy = (oy + 0.5f) * (7.f / 64.f) - 0.5f;
    float ux = (ox + 0.5f) * (7.f / 64.f) - 0.5f;
    float fy = floorf(uy), fx = floorf(ux);
    int y0 = (int)fy, x0 = (int)fx;
    float ty = uy - fy, tx = ux - fx;
    int y0c = min(6, max(0, y0)),     y1c = min(6, max(0, y0 + 1));
    int x0c = min(6, max(0, x0)),     x1c = min(6, max(0, x0 + 1));
    float v00 = p[y0c * 7 + x0c], v01 = p[y0c * 7 + x1c];
    float v10 = p[y1c * 7 + x0c], v11 = p[y1c * 7 + x1c];
    return (v00 * (1.f - tx) + v01 * tx) * (1.f - ty)
         + (v10 * (1.f - tx) + v11 * tx) * ty;
}

__global__ __launch_bounds__(256) void pb_kernel(
    const float* __restrict__ an, const float* __restrict__ ah, const float* __restrict__ aw)
{
    int nh = blockIdx.z, g = blockIdx.y;
    int n = blockIdx.x * 256 + threadIdx.x;
    int h = n >> 6, w = n & 63;
    float v = bilin7(an + (nh * AGg + g) * 49, h, w)
            + ah[(nh * AGg + g) * Hh + h] + aw[(nh * AGg + g) * Ww + w];
    g_pb[(size_t)(nh * AGg + g) * Nn + n] = v;
}

__global__ __launch_bounds__(256) void ab_kernel(
    const float* __restrict__ na, const float* __restrict__ ha, const float* __restrict__ wa)
{
    int nh = blockIdx.z, g = blockIdx.y;
    int n = blockIdx.x * 256 + threadIdx.x;
    int h = n >> 6, w = n & 63;
    float v = bilin7(na + (nh * AGg + g) * 49, h, w)
            + ha[(nh * Hh + h) * AGg + g] + wa[(nh * Ww + w) * AGg + g];
    g_ab[(size_t)(nh * AGg + g) * Nn + n] = v;
}

// ---------------- fused attention-1: logits + online softmax + P*V^T ---------
__global__ __launch_bounds__(256) void attn1_fused()
{
    int bh = blockIdx.x; int b = bh >> 3, nh = bh & 7;
    __shared__ float a_s[32][64];     // a[kd][g]
    __shared__ float S[64][68];       // logits -> probs
    __shared__ float k_s[32][65];
    __shared__ float v_s[64][33];
    __shared__ float m_sh[64], l_sh[64], fact[64];
    int t = threadIdx.x;
    int lane = t & 31, wid = t >> 5;

    for (int i = t; i < 2048; i += 256)
        a_s[i >> 6][i & 63] = g_a[((b * NHh + nh) * KDd) * AGg + i];
    if (t < 64) { m_sh[t] = -1e30f; l_sh[t] = 0.f; }

    const float* kbase = g_qkv + (size_t)(b * 768 + nh * 96 + 32) * Nn;
    const float* vbase = g_qkv + (size_t)(b * 768 + nh * 96 + 64) * Nn;
    const float* pbase = g_pb + (size_t)nh * AGg * Nn;
    const float scale = 0.17677669529663687f;

    float acc[8];
    #pragma unroll
    for (int j = 0; j < 8; j++) acc[j] = 0.f;

    int ln = t & 63, gs = t >> 6;

    for (int n0 = 0; n0 < Nn; n0 += 64) {
        for (int i = t; i < 2048; i += 256) {
            int ck = i >> 6, cn = i & 63;
            k_s[ck][cn] = kbase[(size_t)ck * Nn + n0 + cn];
            v_s[cn][ck] = vbase[(size_t)ck * Nn + n0 + cn];
        }
        __syncthreads();
        {
            float kcol[32];
            #pragma unroll
            for (int c = 0; c < 32; c++) kcol[c] = k_s[c][ln];
            float accl[16];
            #pragma unroll
            for (int gi = 0; gi < 16; gi++) accl[gi] = 0.f;
            #pragma unroll
            for (int c = 0; c < 32; c++) {
                float kc = kcol[c];
                const float4* arow = (const float4*)&a_s[c][gs * 16];
                float4 a0 = arow[0], a1 = arow[1], a2 = arow[2], a3 = arow[3];
                accl[0]  += kc * a0.x; accl[1]  += kc * a0.y;
                accl[2]  += kc * a0.z; accl[3]  += kc * a0.w;
                accl[4]  += kc * a1.x; accl[5]  += kc * a1.y;
                accl[6]  += kc * a1.z; accl[7]  += kc * a1.w;
                accl[8]  += kc * a2.x; accl[9]  += kc * a2.y;
                accl[10] += kc * a2.z; accl[11] += kc * a2.w;
                accl[12] += kc * a3.x; accl[13] += kc * a3.y;
                accl[14] += kc * a3.z; accl[15] += kc * a3.w;
            }
            #pragma unroll
            for (int gi = 0; gi < 16; gi++) {
                int g = gs * 16 + gi;
                S[g][ln] = accl[gi] * scale + pbase[(size_t)g * Nn + n0 + ln];
            }
        }
        __syncthreads();
        #pragma unroll
        for (int j = 0; j < 8; j++) {
            int g = wid * 8 + j;
            float v0 = S[g][lane], v1 = S[g][lane + 32];
            float mx = fmaxf(v0, v1);
            #pragma unroll
            for (int o = 16; o > 0; o >>= 1) mx = fmaxf(mx, __shfl_xor_sync(~0u, mx, o));
            float mold = m_sh[g];
            float mnew = fmaxf(mold, mx);
            float e0 = __expf(v0 - mnew), e1 = __expf(v1 - mnew);
            S[g][lane] = e0; S[g][lane + 32] = e1;
            float s = e0 + e1;
            #pragma unroll
            for (int o = 16; o > 0; o >>= 1) s += __shfl_xor_sync(~0u, s, o);
            if (lane == 0) {
                float f = __expf(mold - mnew);
                l_sh[g] = l_sh[g] * f + s;
                m_sh[g] = mnew;
                fact[g] = f;
            }
        }
        __syncthreads();
        {
            float a2[8];
            #pragma unroll
            for (int j = 0; j < 8; j++) a2[j] = acc[j] * fact[wid * 8 + j];
            #pragma unroll 4
            for (int nb = 0; nb < 64; nb += 4) {
                float vv0 = v_s[nb + 0][lane], vv1 = v_s[nb + 1][lane];
                float vv2 = v_s[nb + 2][lane], vv3 = v_s[nb + 3][lane];
                #pragma unroll
                for (int j = 0; j < 8; j++) {
                    float4 s4 = *(const float4*)&S[wid * 8 + j][nb];
                    a2[j] += s4.x * vv0 + s4.y * vv1 + s4.z * vv2 + s4.w * vv3;
                }
            }
            #pragma unroll
            for (int j = 0; j < 8; j++) acc[j] = a2[j];
        }
        __syncthreads();
    }
    #pragma unroll
    for (int j = 0; j < 8; j++) {
        int g = wid * 8 + j;
        g_attn[((b * NHh + nh) * AGg + g) * KDd + lane] = acc[j] / l_sh[g];
    }
}

// ---------------- fused attention-2: softmax over AG + output contraction ----
__global__ __launch_bounds__(256) void attn2_out_kernel()
{
    int b = blockIdx.z, nh = blockIdx.y;
    int n = blockIdx.x * 256 + threadIdx.x;
    int t = threadIdx.x;
    __shared__ float a_s[32][64];
    __shared__ float at_s[64][32];
    for (int i = t; i < 2048; i += 256) {
        a_s[i >> 6][i & 63]  = g_a[((b * NHh + nh) * KDd) * AGg + i];
        at_s[i >> 5][i & 31] = g_attn[((b * NHh + nh) * AGg) * KDd + i];
    }
    __syncthreads();
    float qreg[32];
    #pragma unroll
    for (int kd = 0; kd < 32; kd++)
        qreg[kd] = g_qkv[((size_t)(b * 768 + nh * 96 + kd)) * Nn + n];
    const float scale = 0.17677669529663687f;
    float lg[64];
    #pragma unroll
    for (int g = 0; g < 64; g++) {
        float acc = 0.f;
        #pragma unroll
        for (int kd = 0; kd < 32; kd++) acc += qreg[kd] * a_s[kd][g];
        lg[g] = acc * scale + g_ab[(size_t)(nh * AGg + g) * Nn + n];
    }
    float mx = -1e30f;
    #pragma unroll
    for (int g = 0; g < 64; g++) mx = fmaxf(mx, lg[g]);
    float sum = 0.f;
    #pragma unroll
    for (int g = 0; g < 64; g++) { lg[g] = __expf(lg[g] - mx); sum += lg[g]; }
    float inv = 1.f / sum;
    #pragma unroll
    for (int kd = 0; kd < 32; kd++) {
        float acc = 0.f;
        #pragma unroll
        for (int g = 0; g < 64; g++) acc += lg[g] * at_s[g][kd];
        g_out[((size_t)(b * Cc + nh * KDd + kd)) * Nn + n] = acc * inv;
    }
}

// ---------------- depthwise 3x3 pe conv + BN, added into g_out ---------------
__global__ __launch_bounds__(256) void pe_kernel(
    const float* __restrict__ pw, const float* __restrict__ bnp)
{
    int b = blockIdx.z, c = blockIdx.y;
    int n = blockIdx.x * 256 + threadIdx.x;
    int h = n >> 6, w = n & 63;
    const float* vb = g_qkv + (size_t)(b * 768 + (c >> 5) * 96 + 64 + (c & 31)) * Nn;
    float acc = 0.f;
    #pragma unroll
    for (int dy = -1; dy <= 1; dy++) {
        int hy = h + dy; if (hy < 0 || hy >= 64) continue;
        #pragma unroll
        for (int dx = -1; dx <= 1; dx++) {
            int wx = w + dx; if (wx < 0 || wx >= 64) continue;
            acc += vb[hy * 64 + wx] * pw[c * 9 + (dy + 1) * 3 + (dx + 1)];
        }
    }
    float gg = bnp[c], bb = bnp[Cc + c], mm = bnp[2 * Cc + c], vv = bnp[3 * Cc + c];
    float inv = gg * rsqrtf(vv + 1e-5f);
    g_out[(size_t)(b * Cc + c) * Nn + n] += acc * inv + (bb - mm * inv);
}

// -----------------------------------------------------------------------------
extern "C" void kernel_launch(void* const* d_in, const int* in_sizes, int n_in,
                              void* d_out, int out_size)
{
    const float* x       = (const float*)d_in[0];
    const float* qkv_w   = (const float*)d_in[1];
    const float* qkv_bn  = (const float*)d_in[2];
    const float* pe_w    = (const float*)d_in[3];
    const float* pe_bn   = (const float*)d_in[4];
    const float* proj_w  = (const float*)d_in[5];
    const float* proj_bn = (const float*)d_in[6];
    const float* an_bias = (const float*)d_in[7];
    const float* na_bias = (const float*)d_in[8];
    const float* ah_bias = (const float*)d_in[9];
    const float* aw_bias = (const float*)d_in[10];
    const float* ha_bias = (const float*)d_in[11];
    const float* wa_bias = (const float*)d_in[12];
    float* out = (float*)d_out;

    float *qkv_ptr, *out_ptr;
    cudaGetSymbolAddress((void**)&qkv_ptr, g_qkv);
    cudaGetSymbolAddress((void**)&out_ptr, g_out);

    cudaFuncSetAttribute(gemm_mma, cudaFuncAttributeMaxDynamicSharedMemorySize,
                         GEMM_SMEM);

    // 1. qkv GEMM + BN (tf32 mma.sync)
    gemm_mma<<<dim3(32, 6, 16), 256, GEMM_SMEM>>>(x, qkv_w, qkv_bn, qkv_ptr, 768, 256, 4096);
    // 2. pooling -> a
    pool_kernel<<<dim3(64, 16), 256>>>();
    // 3. bias maps
    pb_kernel<<<dim3(16, 64, 8), 256>>>(an_bias, ah_bias, aw_bias);
    ab_kernel<<<dim3(16, 64, 8), 256>>>(na_bias, ha_bias, wa_bias);
    // 4. fused attention-1
    attn1_fused<<<128, 256>>>();
    // 5. fused attention-2 + output
    attn2_out_kernel<<<dim3(16, 8, 16), 256>>>();
    // 6. depthwise pe conv + BN add
    pe_kernel<<<dim3(16, 256, 16), 256>>>(pe_w, pe_bn);
    // 7. proj GEMM + BN (tf32 mma.sync)
    gemm_mma<<<dim3(32, 2, 16), 256, GEMM_SMEM>>>(out_ptr, proj_w, proj_bn, out, 256, 256, 4096);
}